// round 1
// baseline (speedup 1.0000x reference)
#include <cuda_runtime.h>
#include <cstdint>
#include <math.h>

// ---------------- problem constants ----------------
#define NROWS   65536
#define SDIM    256
#define ADIM    129
#define HID     256
#define NSTEP   30
#define EPS_LN  1e-5f

#define TM      32      // rows per CTA
#define RPW     4       // rows per warp (8 warps * 4 = 32)
#define XSTR    132     // padded stride for x / W3p rows (132*4 bytes, 16B aligned)

typedef unsigned long long u64;

// packed fp32x2 helpers (sm_103a FFMA2 — ptxas never auto-fuses this)
__device__ __forceinline__ u64 pk2(float lo, float hi) {
    u64 r; asm("mov.b64 %0,{%1,%2};" : "=l"(r) : "f"(lo), "f"(hi)); return r;
}
__device__ __forceinline__ float2 up2(u64 v) {
    float lo, hi; asm("mov.b64 {%0,%1},%2;" : "=f"(lo), "=f"(hi) : "l"(v));
    float2 f; f.x = lo; f.y = hi; return f;
}
__device__ __forceinline__ void fma2(u64 &d, u64 a, u64 b) {
    asm("fma.rn.f32x2 %0,%1,%2,%0;" : "+l"(d) : "l"(a), "l"(b));
}

// W3 repacked to padded stride 132 so float4 loads are 16B aligned (129-stride is not)
__device__ float g_W3p[HID * XSTR];

__global__ void pack_w3_kernel(const float* __restrict__ W3) {
    int i = blockIdx.x * blockDim.x + threadIdx.x;
    if (i < HID * XSTR) {
        int k = i / XSTR, c = i - k * XSTR;
        g_W3p[i] = (c < ADIM) ? W3[k * ADIM + c] : 0.0f;
    }
}

// K-loop GEMM over a 256-wide output; each lane owns cols [4l..4l+3] and [128+4l..128+4l+3]
// for 4 rows. src is smem, broadcast read per-k.
template<int K, int SSTR>
__device__ __forceinline__ void gemm_tile(const float* __restrict__ Wg,
                                          const float* __restrict__ src,
                                          u64 acc[RPW][4], int rbase, int c0, int c1)
{
    const float* sp0 = src + (rbase + 0) * SSTR;
    const float* sp1 = src + (rbase + 1) * SSTR;
    const float* sp2 = src + (rbase + 2) * SSTR;
    const float* sp3 = src + (rbase + 3) * SSTR;
    #pragma unroll 4
    for (int k = 0; k < K; k++) {
        const float4 wa = *(const float4*)(Wg + (size_t)k * HID + c0);
        const float4 wb = *(const float4*)(Wg + (size_t)k * HID + c1);
        const u64 w0 = pk2(wa.x, wa.y), w1 = pk2(wa.z, wa.w);
        const u64 w2 = pk2(wb.x, wb.y), w3 = pk2(wb.z, wb.w);
        const float v0 = sp0[k], v1 = sp1[k], v2 = sp2[k], v3 = sp3[k];
        const u64 x0 = pk2(v0, v0), x1 = pk2(v1, v1), x2 = pk2(v2, v2), x3 = pk2(v3, v3);
        fma2(acc[0][0], w0, x0); fma2(acc[0][1], w1, x0); fma2(acc[0][2], w2, x0); fma2(acc[0][3], w3, x0);
        fma2(acc[1][0], w0, x1); fma2(acc[1][1], w1, x1); fma2(acc[1][2], w2, x1); fma2(acc[1][3], w3, x1);
        fma2(acc[2][0], w0, x2); fma2(acc[2][1], w1, x2); fma2(acc[2][2], w2, x2); fma2(acc[2][3], w3, x2);
        fma2(acc[3][0], w0, x3); fma2(acc[3][1], w1, x3); fma2(acc[3][2], w2, x3); fma2(acc[3][3], w3, x3);
    }
}

// LayerNorm (two-pass, matching reference) + ReLU + store to smem (stride 256)
__device__ __forceinline__ void ln_relu_store(u64 acc[RPW][4], float* __restrict__ dst,
                                              int rbase,
                                              const float* __restrict__ g,
                                              const float* __restrict__ be,
                                              int c0, int c1)
{
    const float4 ga = *(const float4*)(g + c0);
    const float4 gb = *(const float4*)(g + c1);
    const float4 ba = *(const float4*)(be + c0);
    const float4 bb = *(const float4*)(be + c1);
    #pragma unroll
    for (int i = 0; i < RPW; i++) {
        float2 a0 = up2(acc[i][0]), a1 = up2(acc[i][1]);
        float2 a2 = up2(acc[i][2]), a3 = up2(acc[i][3]);
        float s = ((a0.x + a0.y) + (a1.x + a1.y)) + ((a2.x + a2.y) + (a3.x + a3.y));
        #pragma unroll
        for (int o = 16; o > 0; o >>= 1) s += __shfl_xor_sync(0xffffffffu, s, o);
        const float m = s * (1.0f / 256.0f);
        const float d0 = a0.x - m, d1 = a0.y - m, d2 = a1.x - m, d3 = a1.y - m;
        const float d4 = a2.x - m, d5 = a2.y - m, d6 = a3.x - m, d7 = a3.y - m;
        float ss = ((d0 * d0 + d1 * d1) + (d2 * d2 + d3 * d3)) +
                   ((d4 * d4 + d5 * d5) + (d6 * d6 + d7 * d7));
        #pragma unroll
        for (int o = 16; o > 0; o >>= 1) ss += __shfl_xor_sync(0xffffffffu, ss, o);
        const float inv = rsqrtf(ss * (1.0f / 256.0f) + EPS_LN);
        float4 h0, h1;
        h0.x = fmaxf(d0 * inv * ga.x + ba.x, 0.0f);
        h0.y = fmaxf(d1 * inv * ga.y + ba.y, 0.0f);
        h0.z = fmaxf(d2 * inv * ga.z + ba.z, 0.0f);
        h0.w = fmaxf(d3 * inv * ga.w + ba.w, 0.0f);
        h1.x = fmaxf(d4 * inv * gb.x + bb.x, 0.0f);
        h1.y = fmaxf(d5 * inv * gb.y + bb.y, 0.0f);
        h1.z = fmaxf(d6 * inv * gb.z + bb.z, 0.0f);
        h1.w = fmaxf(d7 * inv * gb.w + bb.w, 0.0f);
        *(float4*)(dst + (rbase + i) * HID + c0) = h0;
        *(float4*)(dst + (rbase + i) * HID + c1) = h1;
    }
}

__global__ void __launch_bounds__(256, 2)
actor_kernel(const float* __restrict__ state,  const float* __restrict__ amask,
             const float* __restrict__ x_init, const float* __restrict__ gumbel,
             const float* __restrict__ W1,     const float* __restrict__ b1,
             const float* __restrict__ g1,     const float* __restrict__ be1,
             const float* __restrict__ W2,     const float* __restrict__ b2,
             const float* __restrict__ g2,     const float* __restrict__ be2,
             const float* __restrict__ b3,     float* __restrict__ out)
{
    extern __shared__ float sm[];
    float* s1 = sm;                    // [TM][256]  state@W1a + b1 (step-invariant)
    float* hb = sm + TM * HID;         // [TM][256]  h buffer (state staging, then h1/h2)
    float* xs = sm + 2 * TM * HID;     // [TM][132]  x (129 live + pad)

    const int lane  = threadIdx.x & 31;
    const int wid   = threadIdx.x >> 5;
    const int rbase = wid * RPW;
    const size_t grow0 = (size_t)blockIdx.x * TM;
    const int c0 = lane * 4;
    const int c1 = 128 + lane * 4;

    // ---- load x rows (stride 129 is unaligned -> scalar coalesced) ----
    #pragma unroll
    for (int i = 0; i < RPW; i++) {
        const int r = rbase + i; const size_t gr = grow0 + r;
        const float* xp = x_init + gr * ADIM;
        #pragma unroll
        for (int j = 0; j < 4; j++) xs[r * XSTR + lane + 32 * j] = xp[lane + 32 * j];
        if (lane == 0) xs[r * XSTR + 128] = xp[128];
    }
    // ---- stage state rows in hb ----
    #pragma unroll
    for (int i = 0; i < RPW; i++) {
        const int r = rbase + i; const size_t gr = grow0 + r;
        const float* sp = state + gr * SDIM;
        *(float4*)(hb + r * HID + c0) = *(const float4*)(sp + c0);
        *(float4*)(hb + r * HID + c1) = *(const float4*)(sp + c1);
    }
    __syncwarp();

    u64 acc[RPW][4];

    // ---- S1 = state @ W1[0:256,:] + b1 (hoisted out of the 30-step loop) ----
    {
        const float4 ba = *(const float4*)(b1 + c0);
        const float4 bb = *(const float4*)(b1 + c1);
        #pragma unroll
        for (int i = 0; i < RPW; i++) {
            acc[i][0] = pk2(ba.x, ba.y); acc[i][1] = pk2(ba.z, ba.w);
            acc[i][2] = pk2(bb.x, bb.y); acc[i][3] = pk2(bb.z, bb.w);
        }
        gemm_tile<SDIM, HID>(W1, hb, acc, rbase, c0, c1);
        #pragma unroll
        for (int i = 0; i < RPW; i++) {
            float2 a0 = up2(acc[i][0]), a1 = up2(acc[i][1]);
            float2 a2 = up2(acc[i][2]), a3 = up2(acc[i][3]);
            float4 v0; v0.x = a0.x; v0.y = a0.y; v0.z = a1.x; v0.w = a1.y;
            float4 v1; v1.x = a2.x; v1.y = a2.y; v1.z = a3.x; v1.w = a3.y;
            *(float4*)(s1 + (rbase + i) * HID + c0) = v0;
            *(float4*)(s1 + (rbase + i) * HID + c1) = v1;
        }
    }
    __syncwarp();

    // ---- 30 diffusion steps (entirely warp-private: no __syncthreads) ----
    for (int s = 0; s < NSTEP; s++) {
        const float t = (float)(NSTEP - 1 - s);

        // layer 1: acc = S1 + t*W1[385,:]; += x @ W1[256:385,:]; LN; ReLU -> hb
        {
            const float4 wa = *(const float4*)(W1 + (size_t)385 * HID + c0);
            const float4 wb = *(const float4*)(W1 + (size_t)385 * HID + c1);
            #pragma unroll
            for (int i = 0; i < RPW; i++) {
                const int r = rbase + i;
                const float4 sa = *(const float4*)(s1 + r * HID + c0);
                const float4 sb = *(const float4*)(s1 + r * HID + c1);
                acc[i][0] = pk2(fmaf(t, wa.x, sa.x), fmaf(t, wa.y, sa.y));
                acc[i][1] = pk2(fmaf(t, wa.z, sa.z), fmaf(t, wa.w, sa.w));
                acc[i][2] = pk2(fmaf(t, wb.x, sb.x), fmaf(t, wb.y, sb.y));
                acc[i][3] = pk2(fmaf(t, wb.z, sb.z), fmaf(t, wb.w, sb.w));
            }
            gemm_tile<ADIM, XSTR>(W1 + (size_t)SDIM * HID, xs, acc, rbase, c0, c1);
            ln_relu_store(acc, hb, rbase, g1, be1, c0, c1);
        }
        __syncwarp();

        // layer 2: acc = b2; += h1 @ W2; LN; ReLU -> hb (safe: reads complete first)
        {
            const float4 ba = *(const float4*)(b2 + c0);
            const float4 bb = *(const float4*)(b2 + c1);
            #pragma unroll
            for (int i = 0; i < RPW; i++) {
                acc[i][0] = pk2(ba.x, ba.y); acc[i][1] = pk2(ba.z, ba.w);
                acc[i][2] = pk2(bb.x, bb.y); acc[i][3] = pk2(bb.z, bb.w);
            }
            gemm_tile<HID, HID>(W2, hb, acc, rbase, c0, c1);
            __syncwarp();
            ln_relu_store(acc, hb, rbase, g2, be2, c0, c1);
        }
        __syncwarp();

        // layer 3: noise = h2 @ W3 + b3 (129 cols; col 128 done redundantly by all lanes)
        {
            u64 a3[RPW][2];
            float aL[RPW];
            const float4 b3v = *(const float4*)(b3 + c0);
            const float  bL  = __ldg(b3 + 128);
            #pragma unroll
            for (int i = 0; i < RPW; i++) {
                a3[i][0] = pk2(b3v.x, b3v.y);
                a3[i][1] = pk2(b3v.z, b3v.w);
                aL[i] = bL;
            }
            const float* sp0 = hb + (rbase + 0) * HID;
            const float* sp1 = hb + (rbase + 1) * HID;
            const float* sp2 = hb + (rbase + 2) * HID;
            const float* sp3 = hb + (rbase + 3) * HID;
            #pragma unroll 4
            for (int k = 0; k < HID; k++) {
                const float4 wv = *(const float4*)(g_W3p + k * XSTR + c0);
                const float  wL = g_W3p[k * XSTR + 128];
                const u64 w0 = pk2(wv.x, wv.y), w1 = pk2(wv.z, wv.w);
                const float v0 = sp0[k], v1 = sp1[k], v2 = sp2[k], v3 = sp3[k];
                const u64 x0 = pk2(v0, v0), x1 = pk2(v1, v1), x2 = pk2(v2, v2), x3 = pk2(v3, v3);
                fma2(a3[0][0], w0, x0); fma2(a3[0][1], w1, x0);
                fma2(a3[1][0], w0, x1); fma2(a3[1][1], w1, x1);
                fma2(a3[2][0], w0, x2); fma2(a3[2][1], w1, x2);
                fma2(a3[3][0], w0, x3); fma2(a3[3][1], w1, x3);
                aL[0] = fmaf(v0, wL, aL[0]); aL[1] = fmaf(v1, wL, aL[1]);
                aL[2] = fmaf(v2, wL, aL[2]); aL[3] = fmaf(v3, wL, aL[3]);
            }
            // x <- x - 0.1 * noise
            #pragma unroll
            for (int i = 0; i < RPW; i++) {
                const int r = rbase + i;
                float4 xo = *(float4*)(xs + r * XSTR + c0);
                const float2 n0 = up2(a3[i][0]), n1 = up2(a3[i][1]);
                xo.x = xo.x - 0.1f * n0.x;
                xo.y = xo.y - 0.1f * n0.y;
                xo.z = xo.z - 0.1f * n1.x;
                xo.w = xo.w - 0.1f * n1.y;
                *(float4*)(xs + r * XSTR + c0) = xo;
                if (lane == 0) xs[r * XSTR + 128] = xs[r * XSTR + 128] - 0.1f * aL[i];
            }
        }
        __syncwarp();
    }

    // ---- epilogue: masked gumbel softmax argmax (straight-through) + tanh ----
    #pragma unroll
    for (int i = 0; i < RPW; i++) {
        const int r = rbase + i; const size_t gr = grow0 + r;
        const float4 xv = *(const float4*)(xs + r * XSTR + c0);
        const float4 mk = *(const float4*)(amask  + gr * 128 + c0);
        const float4 gn = *(const float4*)(gumbel + gr * 128 + c0);
        float z[4];
        z[0] = xv.x + (1.0f - mk.x) * (-1e9f) + gn.x;
        z[1] = xv.y + (1.0f - mk.y) * (-1e9f) + gn.y;
        z[2] = xv.z + (1.0f - mk.z) * (-1e9f) + gn.z;
        z[3] = xv.w + (1.0f - mk.w) * (-1e9f) + gn.w;
        float best = z[0]; int bi = c0;
        #pragma unroll
        for (int j = 1; j < 4; j++) if (z[j] > best) { best = z[j]; bi = c0 + j; }
        #pragma unroll
        for (int o = 16; o > 0; o >>= 1) {
            float ov = __shfl_xor_sync(0xffffffffu, best, o);
            int   oi = __shfl_xor_sync(0xffffffffu, bi,   o);
            if (ov > best || (ov == best && oi < bi)) { best = ov; bi = oi; }
        }
        float e[4]; float sl = 0.0f;
        #pragma unroll
        for (int j = 0; j < 4; j++) { e[j] = expf(z[j] - best); sl += e[j]; }
        #pragma unroll
        for (int o = 16; o > 0; o >>= 1) sl += __shfl_xor_sync(0xffffffffu, sl, o);
        #pragma unroll
        for (int j = 0; j < 4; j++) {
            const float p  = e[j] / sl;
            const float yh = (c0 + j == bi) ? 1.0f : 0.0f;
            const float tv = yh + p;             // (y_hard + y_soft) - y_soft, exactly as ref
            out[gr * ADIM + c0 + j] = tv - p;
        }
        if (lane == 0) out[gr * ADIM + 128] = tanhf(xs[r * XSTR + 128]);
    }
}

#define SMEM_BYTES ((2 * TM * HID + TM * XSTR) * sizeof(float))  // 82432 B

extern "C" void kernel_launch(void* const* d_in, const int* in_sizes, int n_in,
                              void* d_out, int out_size)
{
    const float* state  = (const float*)d_in[0];
    const float* amask  = (const float*)d_in[1];
    const float* x_init = (const float*)d_in[2];
    const float* gumbel = (const float*)d_in[3];
    const float* W1     = (const float*)d_in[4];
    const float* b1     = (const float*)d_in[5];
    const float* g1     = (const float*)d_in[6];
    const float* be1    = (const float*)d_in[7];
    const float* W2     = (const float*)d_in[8];
    const float* b2     = (const float*)d_in[9];
    const float* g2     = (const float*)d_in[10];
    const float* be2    = (const float*)d_in[11];
    const float* W3     = (const float*)d_in[12];
    const float* b3     = (const float*)d_in[13];
    float* out          = (float*)d_out;

    pack_w3_kernel<<<(HID * XSTR + 255) / 256, 256>>>(W3);

    cudaFuncSetAttribute(actor_kernel,
                         cudaFuncAttributeMaxDynamicSharedMemorySize,
                         (int)SMEM_BYTES);

    actor_kernel<<<NROWS / TM, 256, SMEM_BYTES>>>(
        state, amask, x_init, gumbel,
        W1, b1, g1, be1, W2, b2, g2, be2, b3, out);
}

// round 2
// speedup vs baseline: 2.0493x; 2.0493x over previous
#include <cuda_runtime.h>
#include <cstdint>
#include <math.h>

// ---------------- problem constants ----------------
#define NROWS   65536
#define SDIM    256
#define ADIM    129
#define HID     256
#define NSTEP   30
#define EPS_LN  1e-5f

#define TM      32      // rows per CTA
#define RPW     8       // rows per warp (4 warps * 8 = 32)
#define NWARP   4
#define XSTR    132     // padded float stride for x rows (16B-aligned, zero pad 129..131)

typedef unsigned long long u64;

// packed fp32x2 helpers (sm_103a FFMA2)
__device__ __forceinline__ u64 pk2(float lo, float hi) {
    u64 r; asm("mov.b64 %0,{%1,%2};" : "=l"(r) : "f"(lo), "f"(hi)); return r;
}
__device__ __forceinline__ float2 up2(u64 v) {
    float lo, hi; asm("mov.b64 {%0,%1},%2;" : "=f"(lo), "=f"(hi) : "l"(v));
    float2 f; f.x = lo; f.y = hi; return f;
}
__device__ __forceinline__ void fma2(u64 &d, u64 a, u64 b) {
    asm("fma.rn.f32x2 %0,%1,%2,%0;" : "+l"(d) : "l"(a), "l"(b));
}

// W1 x-part (rows 256..384) zero-padded to 132 k-rows, stride 256
__device__ float g_W1xp[132 * HID];
// W3 zero-padded to 132 cols, stride 132
__device__ float g_W3p[HID * 132];

__global__ void pack_w1x_kernel(const float* __restrict__ W1) {
    int i = blockIdx.x * blockDim.x + threadIdx.x;
    if (i < 132 * HID) {
        int k = i / HID, c = i - k * HID;
        g_W1xp[i] = (k < 129) ? W1[(size_t)(SDIM + k) * HID + c] : 0.0f;
    }
}
__global__ void pack_w3_kernel(const float* __restrict__ W3) {
    int i = blockIdx.x * blockDim.x + threadIdx.x;
    if (i < HID * 132) {
        int k = i / 132, c = i - k * 132;
        g_W3p[i] = (c < ADIM) ? W3[k * ADIM + c] : 0.0f;
    }
}

// ---- load one 4-k block of weights (256-wide row): 8 float4 per lane ----
__device__ __forceinline__ void loadw(float4 w[8], const float* __restrict__ Wg,
                                      int jb, int c0, int c1) {
    const float* p = Wg + (size_t)jb * 4 * HID;
    #pragma unroll
    for (int j = 0; j < 4; j++) {
        w[2*j]   = *(const float4*)(p + j * HID + c0);
        w[2*j+1] = *(const float4*)(p + j * HID + c1);
    }
}

// ---- FMA one 4-k block over 8 rows, 8 cols/lane ----
__device__ __forceinline__ void fmablock(const float4 w[8], const float* __restrict__ src,
                                         int sstr, int jb, u64 acc[RPW][4]) {
    float4 av[RPW];
    #pragma unroll
    for (int i = 0; i < RPW; i++)
        av[i] = *(const float4*)(src + i * sstr + jb * 4);
    #pragma unroll
    for (int j = 0; j < 4; j++) {
        const u64 w0 = pk2(w[2*j].x,   w[2*j].y);
        const u64 w1 = pk2(w[2*j].z,   w[2*j].w);
        const u64 w2 = pk2(w[2*j+1].x, w[2*j+1].y);
        const u64 w3 = pk2(w[2*j+1].z, w[2*j+1].w);
        #pragma unroll
        for (int i = 0; i < RPW; i++) {
            const float v = (j == 0) ? av[i].x : (j == 1) ? av[i].y
                          : (j == 2) ? av[i].z : av[i].w;
            const u64 xv = pk2(v, v);
            fma2(acc[i][0], w0, xv);
            fma2(acc[i][1], w1, xv);
            fma2(acc[i][2], w2, xv);
            fma2(acc[i][3], w3, xv);
        }
    }
}

// ---- K-loop GEMM with register ping-pong weight prefetch ----
template<int KB>
__device__ __forceinline__ void gemm8(const float* __restrict__ Wg,
                                      const float* __restrict__ src, int sstr,
                                      u64 acc[RPW][4], int c0, int c1)
{
    float4 wA[8], wB[8];
    loadw(wA, Wg, 0, c0, c1);
    #pragma unroll 1
    for (int jb = 0; jb < KB; jb += 2) {
        if (jb + 1 < KB) loadw(wB, Wg, jb + 1, c0, c1);
        fmablock(wA, src, sstr, jb, acc);
        if (jb + 1 < KB) {
            if (jb + 2 < KB) loadw(wA, Wg, jb + 2, c0, c1);
            fmablock(wB, src, sstr, jb + 1, acc);
        }
    }
}

// ---- layer-3 variant: 4 cols/lane, weights from g_W3p (stride 132) ----
__device__ __forceinline__ void loadw3(float4 w[4], int jb, int c0) {
    #pragma unroll
    for (int j = 0; j < 4; j++)
        w[j] = *(const float4*)(g_W3p + (size_t)(jb * 4 + j) * 132 + c0);
}
__device__ __forceinline__ void fmablock3(const float4 w[4], const float* __restrict__ src,
                                          int jb, u64 acc[RPW][2]) {
    float4 av[RPW];
    #pragma unroll
    for (int i = 0; i < RPW; i++)
        av[i] = *(const float4*)(src + i * HID + jb * 4);
    #pragma unroll
    for (int j = 0; j < 4; j++) {
        const u64 w0 = pk2(w[j].x, w[j].y);
        const u64 w1 = pk2(w[j].z, w[j].w);
        #pragma unroll
        for (int i = 0; i < RPW; i++) {
            const float v = (j == 0) ? av[i].x : (j == 1) ? av[i].y
                          : (j == 2) ? av[i].z : av[i].w;
            const u64 xv = pk2(v, v);
            fma2(acc[i][0], w0, xv);
            fma2(acc[i][1], w1, xv);
        }
    }
}

// LayerNorm (two-pass) + ReLU + store to smem (stride 256)
__device__ __forceinline__ void ln_relu_store(u64 acc[RPW][4], float* __restrict__ dst,
                                              const float* __restrict__ g,
                                              const float* __restrict__ be,
                                              int c0, int c1)
{
    const float4 ga = *(const float4*)(g + c0);
    const float4 gb = *(const float4*)(g + c1);
    const float4 ba = *(const float4*)(be + c0);
    const float4 bb = *(const float4*)(be + c1);
    #pragma unroll
    for (int i = 0; i < RPW; i++) {
        float2 a0 = up2(acc[i][0]), a1 = up2(acc[i][1]);
        float2 a2 = up2(acc[i][2]), a3 = up2(acc[i][3]);
        float s = ((a0.x + a0.y) + (a1.x + a1.y)) + ((a2.x + a2.y) + (a3.x + a3.y));
        #pragma unroll
        for (int o = 16; o > 0; o >>= 1) s += __shfl_xor_sync(0xffffffffu, s, o);
        const float m = s * (1.0f / 256.0f);
        const float d0 = a0.x - m, d1 = a0.y - m, d2 = a1.x - m, d3 = a1.y - m;
        const float d4 = a2.x - m, d5 = a2.y - m, d6 = a3.x - m, d7 = a3.y - m;
        float ss = ((d0*d0 + d1*d1) + (d2*d2 + d3*d3)) + ((d4*d4 + d5*d5) + (d6*d6 + d7*d7));
        #pragma unroll
        for (int o = 16; o > 0; o >>= 1) ss += __shfl_xor_sync(0xffffffffu, ss, o);
        const float inv = rsqrtf(ss * (1.0f / 256.0f) + EPS_LN);
        float4 h0, h1;
        h0.x = fmaxf(d0 * inv * ga.x + ba.x, 0.0f);
        h0.y = fmaxf(d1 * inv * ga.y + ba.y, 0.0f);
        h0.z = fmaxf(d2 * inv * ga.z + ba.z, 0.0f);
        h0.w = fmaxf(d3 * inv * ga.w + ba.w, 0.0f);
        h1.x = fmaxf(d4 * inv * gb.x + bb.x, 0.0f);
        h1.y = fmaxf(d5 * inv * gb.y + bb.y, 0.0f);
        h1.z = fmaxf(d6 * inv * gb.z + bb.z, 0.0f);
        h1.w = fmaxf(d7 * inv * gb.w + bb.w, 0.0f);
        *(float4*)(dst + i * HID + c0) = h0;
        *(float4*)(dst + i * HID + c1) = h1;
    }
}

__global__ void __launch_bounds__(128, 2)
actor_kernel(const float* __restrict__ state,  const float* __restrict__ amask,
             const float* __restrict__ x_init, const float* __restrict__ gumbel,
             const float* __restrict__ W1,     const float* __restrict__ b1,
             const float* __restrict__ g1,     const float* __restrict__ be1,
             const float* __restrict__ W2,     const float* __restrict__ b2,
             const float* __restrict__ g2,     const float* __restrict__ be2,
             const float* __restrict__ b3,     float* __restrict__ out)
{
    extern __shared__ float sm[];
    float* s1 = sm;                    // [TM][256] state@W1a + b1 (step-invariant)
    float* hb = sm + TM * HID;         // [TM][256] h buffer
    float* xs = sm + 2 * TM * HID;     // [TM][132] x (129 live + zero pad)

    const int lane  = threadIdx.x & 31;
    const int wid   = threadIdx.x >> 5;
    const int rbase = wid * RPW;
    const size_t grow0 = (size_t)blockIdx.x * TM;
    const int c0 = lane * 4;
    const int c1 = 128 + lane * 4;

    float* xw  = xs + rbase * XSTR;    // warp's x rows
    float* hw  = hb + rbase * HID;     // warp's h rows
    float* s1w = s1 + rbase * HID;

    // ---- load x rows (stride 129, scalar coalesced) + zero pads ----
    #pragma unroll
    for (int i = 0; i < RPW; i++) {
        const size_t gr = grow0 + rbase + i;
        const float* xp = x_init + gr * ADIM;
        #pragma unroll
        for (int j = 0; j < 4; j++) xw[i * XSTR + lane + 32 * j] = xp[lane + 32 * j];
        if (lane == 0) xw[i * XSTR + 128] = xp[128];
        if (lane >= 1 && lane <= 3) xw[i * XSTR + 128 + lane] = 0.0f;
    }
    // ---- stage state rows in hb ----
    #pragma unroll
    for (int i = 0; i < RPW; i++) {
        const float* sp = state + (grow0 + rbase + i) * SDIM;
        *(float4*)(hw + i * HID + c0) = *(const float4*)(sp + c0);
        *(float4*)(hw + i * HID + c1) = *(const float4*)(sp + c1);
    }
    __syncwarp();

    // step-invariant preloads
    float w128[8];  // W3 col 128, lane-strided over k
    #pragma unroll
    for (int j = 0; j < 8; j++) w128[j] = g_W3p[(size_t)(lane + 32 * j) * 132 + 128];
    const float b3L = __ldg(b3 + 128);

    u64 acc[RPW][4];

    // ---- S1 = state @ W1[0:256,:] + b1 (hoisted) ----
    {
        const float4 ba = *(const float4*)(b1 + c0);
        const float4 bb = *(const float4*)(b1 + c1);
        #pragma unroll
        for (int i = 0; i < RPW; i++) {
            acc[i][0] = pk2(ba.x, ba.y); acc[i][1] = pk2(ba.z, ba.w);
            acc[i][2] = pk2(bb.x, bb.y); acc[i][3] = pk2(bb.z, bb.w);
        }
        gemm8<64>(W1, hw, HID, acc, c0, c1);
        #pragma unroll
        for (int i = 0; i < RPW; i++) {
            float2 a0 = up2(acc[i][0]), a1 = up2(acc[i][1]);
            float2 a2 = up2(acc[i][2]), a3 = up2(acc[i][3]);
            float4 v0; v0.x = a0.x; v0.y = a0.y; v0.z = a1.x; v0.w = a1.y;
            float4 v1; v1.x = a2.x; v1.y = a2.y; v1.z = a3.x; v1.w = a3.y;
            *(float4*)(s1w + i * HID + c0) = v0;
            *(float4*)(s1w + i * HID + c1) = v1;
        }
    }
    __syncwarp();

    // ---- 30 diffusion steps (warp-private, no __syncthreads) ----
    for (int s = 0; s < NSTEP; s++) {
        const float t = (float)(NSTEP - 1 - s);

        // layer 1: acc = S1 + t*W1[385]; += x @ W1x (K=132 padded); LN+ReLU -> hb
        {
            const float4 wa = *(const float4*)(W1 + (size_t)385 * HID + c0);
            const float4 wb = *(const float4*)(W1 + (size_t)385 * HID + c1);
            #pragma unroll
            for (int i = 0; i < RPW; i++) {
                const float4 sa = *(const float4*)(s1w + i * HID + c0);
                const float4 sb = *(const float4*)(s1w + i * HID + c1);
                acc[i][0] = pk2(fmaf(t, wa.x, sa.x), fmaf(t, wa.y, sa.y));
                acc[i][1] = pk2(fmaf(t, wa.z, sa.z), fmaf(t, wa.w, sa.w));
                acc[i][2] = pk2(fmaf(t, wb.x, sb.x), fmaf(t, wb.y, sb.y));
                acc[i][3] = pk2(fmaf(t, wb.z, sb.z), fmaf(t, wb.w, sb.w));
            }
            gemm8<33>(g_W1xp, xw, XSTR, acc, c0, c1);
            ln_relu_store(acc, hw, g1, be1, c0, c1);
        }
        __syncwarp();

        // layer 2: acc = b2; += h1 @ W2; LN+ReLU -> hb
        {
            const float4 ba = *(const float4*)(b2 + c0);
            const float4 bb = *(const float4*)(b2 + c1);
            #pragma unroll
            for (int i = 0; i < RPW; i++) {
                acc[i][0] = pk2(ba.x, ba.y); acc[i][1] = pk2(ba.z, ba.w);
                acc[i][2] = pk2(bb.x, bb.y); acc[i][3] = pk2(bb.z, bb.w);
            }
            gemm8<64>(W2, hw, HID, acc, c0, c1);
            __syncwarp();                      // WAR: all lanes done reading hb
            ln_relu_store(acc, hw, g2, be2, c0, c1);
        }
        __syncwarp();

        // layer 3: noise = h2 @ W3 + b3; x -= 0.1*noise
        {
            u64 a3[RPW][2];
            const float4 b3v = *(const float4*)(b3 + c0);
            #pragma unroll
            for (int i = 0; i < RPW; i++) {
                a3[i][0] = pk2(b3v.x, b3v.y);
                a3[i][1] = pk2(b3v.z, b3v.w);
            }
            // main 128 cols (4 per lane), ping-pong prefetch
            {
                float4 wA[4], wB[4];
                loadw3(wA, 0, c0);
                #pragma unroll 1
                for (int jb = 0; jb < 64; jb += 2) {
                    loadw3(wB, jb + 1, c0);
                    fmablock3(wA, hw, jb, a3);
                    if (jb + 2 < 64) loadw3(wA, jb + 2, c0);
                    fmablock3(wB, hw, jb + 1, a3);
                }
            }
            // col 128: lane-strided partial dot + butterfly reduce per row
            float a128[RPW];
            #pragma unroll
            for (int i = 0; i < RPW; i++) a128[i] = 0.0f;
            #pragma unroll
            for (int j = 0; j < 8; j++) {
                #pragma unroll
                for (int i = 0; i < RPW; i++) {
                    const float hv = hw[i * HID + lane + 32 * j];
                    a128[i] = fmaf(hv, w128[j], a128[i]);
                }
            }
            #pragma unroll
            for (int i = 0; i < RPW; i++) {
                #pragma unroll
                for (int o = 16; o > 0; o >>= 1)
                    a128[i] += __shfl_xor_sync(0xffffffffu, a128[i], o);
            }
            // x update
            #pragma unroll
            for (int i = 0; i < RPW; i++) {
                float4 xo = *(float4*)(xw + i * XSTR + c0);
                const float2 n0 = up2(a3[i][0]), n1 = up2(a3[i][1]);
                xo.x -= 0.1f * n0.x;
                xo.y -= 0.1f * n0.y;
                xo.z -= 0.1f * n1.x;
                xo.w -= 0.1f * n1.y;
                *(float4*)(xw + i * XSTR + c0) = xo;
                if (lane == 0)
                    xw[i * XSTR + 128] -= 0.1f * (b3L + a128[i]);
            }
        }
        __syncwarp();
    }

    // ---- epilogue: masked gumbel softmax argmax (straight-through) + tanh ----
    #pragma unroll
    for (int i = 0; i < RPW; i++) {
        const size_t gr = grow0 + rbase + i;
        const float4 xv = *(const float4*)(xw + i * XSTR + c0);
        const float4 mk = *(const float4*)(amask  + gr * 128 + c0);
        const float4 gn = *(const float4*)(gumbel + gr * 128 + c0);
        float z[4];
        z[0] = xv.x + (1.0f - mk.x) * (-1e9f) + gn.x;
        z[1] = xv.y + (1.0f - mk.y) * (-1e9f) + gn.y;
        z[2] = xv.z + (1.0f - mk.z) * (-1e9f) + gn.z;
        z[3] = xv.w + (1.0f - mk.w) * (-1e9f) + gn.w;
        float best = z[0]; int bi = c0;
        #pragma unroll
        for (int j = 1; j < 4; j++) if (z[j] > best) { best = z[j]; bi = c0 + j; }
        #pragma unroll
        for (int o = 16; o > 0; o >>= 1) {
            float ov = __shfl_xor_sync(0xffffffffu, best, o);
            int   oi = __shfl_xor_sync(0xffffffffu, bi,   o);
            if (ov > best || (ov == best && oi < bi)) { best = ov; bi = oi; }
        }
        float e[4]; float sl = 0.0f;
        #pragma unroll
        for (int j = 0; j < 4; j++) { e[j] = expf(z[j] - best); sl += e[j]; }
        #pragma unroll
        for (int o = 16; o > 0; o >>= 1) sl += __shfl_xor_sync(0xffffffffu, sl, o);
        #pragma unroll
        for (int j = 0; j < 4; j++) {
            const float p  = e[j] / sl;
            const float yh = (c0 + j == bi) ? 1.0f : 0.0f;
            const float tv = yh + p;
            out[gr * ADIM + c0 + j] = tv - p;
        }
        if (lane == 0) out[gr * ADIM + 128] = tanhf(xw[i * XSTR + 128]);
    }
}

#define SMEM_BYTES ((2 * TM * HID + TM * XSTR) * sizeof(float))  // 82432 B

extern "C" void kernel_launch(void* const* d_in, const int* in_sizes, int n_in,
                              void* d_out, int out_size)
{
    const float* state  = (const float*)d_in[0];
    const float* amask  = (const float*)d_in[1];
    const float* x_init = (const float*)d_in[2];
    const float* gumbel = (const float*)d_in[3];
    const float* W1     = (const float*)d_in[4];
    const float* b1     = (const float*)d_in[5];
    const float* g1     = (const float*)d_in[6];
    const float* be1    = (const float*)d_in[7];
    const float* W2     = (const float*)d_in[8];
    const float* b2     = (const float*)d_in[9];
    const float* g2     = (const float*)d_in[10];
    const float* be2    = (const float*)d_in[11];
    const float* W3     = (const float*)d_in[12];
    const float* b3     = (const float*)d_in[13];
    float* out          = (float*)d_out;

    pack_w1x_kernel<<<(132 * HID + 255) / 256, 256>>>(W1);
    pack_w3_kernel<<<(HID * 132 + 255) / 256, 256>>>(W3);

    cudaFuncSetAttribute(actor_kernel,
                         cudaFuncAttributeMaxDynamicSharedMemorySize,
                         (int)SMEM_BYTES);

    actor_kernel<<<NROWS / TM, 128, SMEM_BYTES>>>(
        state, amask, x_init, gumbel,
        W1, b1, g1, be1, W2, b2, g2, be2, b3, out);
}